// round 3
// baseline (speedup 1.0000x reference)
#include <cuda_runtime.h>
#include <cub/cub.cuh>
#include <cstdint>

namespace {
constexpr int BATCH = 8;
constexpr int NANCH = 262144;         // 2^18
constexpr int TOTAL = BATCH * NANCH;  // 2,097,152
constexpr int TOPK  = 6000;
constexpr int NOUT  = 1000;
constexpr int COLB  = (TOPK + 63) / 64;  // 94
constexpr float THR = 0.7f;
constexpr int TAIL_BITS = TOPK - (COLB - 1) * 64;  // 48
}

// -------- device-global scratch (no allocation allowed in kernel_launch) ----
__device__ unsigned long long g_keys_in [TOTAL];
__device__ unsigned long long g_keys_out[TOTAL];
__device__ int                g_vals_in [TOTAL];
__device__ int                g_vals_out[TOTAL];
__device__ __align__(16) float g_boxes[BATCH * TOPK * 4];
__device__ unsigned long long g_mask[(size_t)BATCH * TOPK * COLB];  // ~36 MB
__device__ unsigned char      g_temp[96 * 1024 * 1024];             // cub temp

// -------- 1. extract scores -> sortable 35-bit composite keys ---------------
// key = ((7-b) << 32) | float_bits(score). Scores are softmax outputs (>0),
// so fp32 bit pattern is monotone in value. Descending stable radix sort then
// yields batch-0-first blocks, each sorted desc by score with ties broken by
// lower original index — exactly jax.lax.top_k semantics.
__global__ void extract_kernel(const float* __restrict__ rpn_class) {
    int g = blockIdx.x * blockDim.x + threadIdx.x;
    if (g >= TOTAL) return;
    float s = __ldg(&rpn_class[2 * g + 1]);
    unsigned int bits = __float_as_uint(s);
    int b = g >> 18;
    g_keys_in[g] = ((unsigned long long)(7 - b) << 32) | (unsigned long long)bits;
    g_vals_in[g] = g & (NANCH - 1);
}

// -------- 2. gather top-6000, apply deltas, clip -----------------------------
__global__ void boxes_kernel(const float* __restrict__ rpn_bbox,
                             const float* __restrict__ anchors) {
    int t = blockIdx.x * blockDim.x + threadIdx.x;
    if (t >= BATCH * TOPK) return;
    int b = t / TOPK;
    int k = t - b * TOPK;
    int idx = g_vals_out[b * NANCH + k];
    int src = (b * NANCH + idx) * 4;
    float4 a = *reinterpret_cast<const float4*>(anchors  + src);
    float4 d = *reinterpret_cast<const float4*>(rpn_bbox + src);
    float dy = d.x * 0.1f, dx = d.y * 0.1f;
    float dh = d.z * 0.2f, dw = d.w * 0.2f;
    float h = a.z - a.x;
    float w = a.w - a.y;
    float cy = a.x + 0.5f * h;
    float cx = a.y + 0.5f * w;
    cy = cy + dy * h;
    cx = cx + dx * w;
    h = h * expf(dh);
    w = w * expf(dw);
    float y1 = fminf(fmaxf(cy - 0.5f * h, 0.f), 1.f);
    float x1 = fminf(fmaxf(cx - 0.5f * w, 0.f), 1.f);
    float y2 = fminf(fmaxf(cy + 0.5f * h, 0.f), 1.f);
    float x2 = fminf(fmaxf(cx + 0.5f * w, 0.f), 1.f);
    reinterpret_cast<float4*>(g_boxes)[t] = make_float4(y1, x1, y2, x2);
}

// -------- 3. pairwise IoU suppression bitmask (torchvision layout) ----------
__global__ void iou_kernel() {
    int b        = blockIdx.z;
    int colStart = blockIdx.x * 64;
    int rowStart = blockIdx.y * 64;
    __shared__ float4 colBox[64];
    int tid = threadIdx.x;
    int ncols = min(64, TOPK - colStart);
    int nrows = min(64, TOPK - rowStart);
    if (tid < ncols)
        colBox[tid] = reinterpret_cast<const float4*>(g_boxes)[b * TOPK + colStart + tid];
    __syncthreads();
    if (tid >= nrows) return;
    int i = rowStart + tid;
    float4 rb = reinterpret_cast<const float4*>(g_boxes)[b * TOPK + i];
    float area1 = (rb.z - rb.x) * (rb.w - rb.y);
    unsigned long long m = 0;
    for (int j = 0; j < ncols; ++j) {
        float4 cb = colBox[j];
        float y1 = fmaxf(rb.x, cb.x);
        float x1 = fmaxf(rb.y, cb.y);
        float y2 = fminf(rb.z, cb.z);
        float x2 = fminf(rb.w, cb.w);
        float inter = fmaxf(y2 - y1, 0.f) * fmaxf(x2 - x1, 0.f);
        float area2 = (cb.z - cb.x) * (cb.w - cb.y);
        float iou = inter / (area1 + area2 - inter + 1e-9f);
        if (iou > THR) m |= 1ull << j;
    }
    g_mask[((size_t)(b * TOPK + i)) * COLB + blockIdx.x] = m;
}

// -------- 4. sequential sweep (one warp/batch) + output write ---------------
// Walk bits in sorted order, skipping suppressed ones via ffsll. Each kept box
// ORs its 94-word suppression row into the shared 'removed' bitmask.
__global__ void sweep_kernel(float* __restrict__ out) {
    int b = blockIdx.x;
    __shared__ unsigned long long removed[COLB];
    __shared__ int kept[NOUT];
    __shared__ int kcount;
    int tid = threadIdx.x;
    if (tid < COLB)
        removed[tid] = (tid == COLB - 1) ? ~((1ull << TAIL_BITS) - 1ull) : 0ull;
    if (tid == 0) kcount = 0;
    __syncthreads();

    if (tid < 32) {
        int cnt = 0;
        for (int w = 0; w < COLB && cnt < NOUT; ++w) {
            unsigned long long avail = ~removed[w];
            while (avail && cnt < NOUT) {
                int bit = __ffsll((long long)avail) - 1;
                avail &= avail - 1;  // clear taken bit (handles zero-area self-IoU=0)
                int i = (w << 6) + bit;
                if (tid == 0) kept[cnt] = i;
                cnt++;
                const unsigned long long* row = &g_mask[((size_t)(b * TOPK + i)) * COLB];
                unsigned long long myw = 0;
                for (int ww = tid; ww < COLB; ww += 32) {
                    unsigned long long rv = row[ww];
                    removed[ww] |= rv;
                    if (ww == w) myw = rv;
                }
                unsigned long long rw = __shfl_sync(0xffffffffu, myw, w & 31);
                avail &= ~rw;
                __syncwarp();
            }
        }
        if (tid == 0) kcount = cnt;
    }
    __syncthreads();

    int kc = kcount;
    for (int k = tid; k < NOUT; k += blockDim.x) {
        float4 v = make_float4(0.f, 0.f, 0.f, 0.f);
        if (k < kc)
            v = reinterpret_cast<const float4*>(g_boxes)[b * TOPK + kept[k]];
        reinterpret_cast<float4*>(out)[b * NOUT + k] = v;
    }
}

// -------- launch --------------------------------------------------------------
extern "C" void kernel_launch(void* const* d_in, const int* in_sizes, int n_in,
                              void* d_out, int out_size) {
    const float* rpn_class = (const float*)d_in[0];
    const float* rpn_bbox  = (const float*)d_in[1];
    const float* anchors   = (const float*)d_in[2];
    float* out = (float*)d_out;

    void *kin, *kout, *vin, *vout, *tmp;
    cudaGetSymbolAddress(&kin,  g_keys_in);
    cudaGetSymbolAddress(&kout, g_keys_out);
    cudaGetSymbolAddress(&vin,  g_vals_in);
    cudaGetSymbolAddress(&vout, g_vals_out);
    cudaGetSymbolAddress(&tmp,  g_temp);

    extract_kernel<<<(TOTAL + 255) / 256, 256>>>(rpn_class);

    size_t temp_bytes = 0;
    cub::DeviceRadixSort::SortPairsDescending(
        nullptr, temp_bytes,
        (const unsigned long long*)kin, (unsigned long long*)kout,
        (const int*)vin, (int*)vout, TOTAL, 0, 35);
    if (temp_bytes <= sizeof(g_temp)) {
        cub::DeviceRadixSort::SortPairsDescending(
            tmp, temp_bytes,
            (const unsigned long long*)kin, (unsigned long long*)kout,
            (const int*)vin, (int*)vout, TOTAL, 0, 35);
    }

    boxes_kernel<<<(BATCH * TOPK + 255) / 256, 256>>>(rpn_bbox, anchors);

    dim3 gmask(COLB, COLB, BATCH);
    iou_kernel<<<gmask, 64>>>();

    sweep_kernel<<<BATCH, 128>>>(out);
}

// round 4
// speedup vs baseline: 1.0004x; 1.0004x over previous
#include <cuda_runtime.h>
#include <cub/cub.cuh>
#include <cstdint>

namespace {
constexpr int BATCH = 8;
constexpr int NANCH = 262144;         // 2^18
constexpr int TOTAL = BATCH * NANCH;  // 2,097,152
constexpr int TOPK  = 6000;
constexpr int NOUT  = 1000;
constexpr int COLB  = (TOPK + 63) / 64;  // 94
constexpr float THR = 0.7f;
constexpr int TAIL_BITS = TOPK - (COLB - 1) * 64;  // 48
}

// -------- device-global scratch (no allocation allowed in kernel_launch) ----
__device__ unsigned long long g_keys_in [TOTAL];
__device__ unsigned long long g_keys_out[TOTAL];
__device__ int                g_vals_in [TOTAL];
__device__ int                g_vals_out[TOTAL];
__device__ __align__(16) float g_boxes[BATCH * TOPK * 4];
__device__ unsigned long long g_mask[(size_t)BATCH * TOPK * COLB];  // ~36 MB
__device__ unsigned char      g_temp[96 * 1024 * 1024];             // cub temp

// -------- 1. extract scores -> sortable 35-bit composite keys ---------------
// key = ((7-b) << 32) | float_bits(score). Scores are softmax outputs (>0),
// so fp32 bit pattern is monotone in value. Descending stable radix sort then
// yields batch-0-first blocks, each sorted desc by score with ties broken by
// lower original index — exactly jax.lax.top_k semantics.
__global__ void extract_kernel(const float* __restrict__ rpn_class) {
    int g = blockIdx.x * blockDim.x + threadIdx.x;
    if (g >= TOTAL) return;
    float s = __ldg(&rpn_class[2 * g + 1]);
    unsigned int bits = __float_as_uint(s);
    int b = g >> 18;
    g_keys_in[g] = ((unsigned long long)(7 - b) << 32) | (unsigned long long)bits;
    g_vals_in[g] = g & (NANCH - 1);
}

// -------- 2. gather top-6000, apply deltas, clip -----------------------------
__global__ void boxes_kernel(const float* __restrict__ rpn_bbox,
                             const float* __restrict__ anchors) {
    int t = blockIdx.x * blockDim.x + threadIdx.x;
    if (t >= BATCH * TOPK) return;
    int b = t / TOPK;
    int k = t - b * TOPK;
    int idx = g_vals_out[b * NANCH + k];
    int src = (b * NANCH + idx) * 4;
    float4 a = *reinterpret_cast<const float4*>(anchors  + src);
    float4 d = *reinterpret_cast<const float4*>(rpn_bbox + src);
    float dy = d.x * 0.1f, dx = d.y * 0.1f;
    float dh = d.z * 0.2f, dw = d.w * 0.2f;
    float h = a.z - a.x;
    float w = a.w - a.y;
    float cy = a.x + 0.5f * h;
    float cx = a.y + 0.5f * w;
    cy = cy + dy * h;
    cx = cx + dx * w;
    h = h * expf(dh);
    w = w * expf(dw);
    float y1 = fminf(fmaxf(cy - 0.5f * h, 0.f), 1.f);
    float x1 = fminf(fmaxf(cx - 0.5f * w, 0.f), 1.f);
    float y2 = fminf(fmaxf(cy + 0.5f * h, 0.f), 1.f);
    float x2 = fminf(fmaxf(cx + 0.5f * w, 0.f), 1.f);
    reinterpret_cast<float4*>(g_boxes)[t] = make_float4(y1, x1, y2, x2);
}

// -------- 3. pairwise IoU suppression bitmask (torchvision layout) ----------
__global__ void iou_kernel() {
    int b        = blockIdx.z;
    int colStart = blockIdx.x * 64;
    int rowStart = blockIdx.y * 64;
    __shared__ float4 colBox[64];
    int tid = threadIdx.x;
    int ncols = min(64, TOPK - colStart);
    int nrows = min(64, TOPK - rowStart);
    if (tid < ncols)
        colBox[tid] = reinterpret_cast<const float4*>(g_boxes)[b * TOPK + colStart + tid];
    __syncthreads();
    if (tid >= nrows) return;
    int i = rowStart + tid;
    float4 rb = reinterpret_cast<const float4*>(g_boxes)[b * TOPK + i];
    float area1 = (rb.z - rb.x) * (rb.w - rb.y);
    unsigned long long m = 0;
    for (int j = 0; j < ncols; ++j) {
        float4 cb = colBox[j];
        float y1 = fmaxf(rb.x, cb.x);
        float x1 = fmaxf(rb.y, cb.y);
        float y2 = fminf(rb.z, cb.z);
        float x2 = fminf(rb.w, cb.w);
        float inter = fmaxf(y2 - y1, 0.f) * fmaxf(x2 - x1, 0.f);
        float area2 = (cb.z - cb.x) * (cb.w - cb.y);
        float iou = inter / (area1 + area2 - inter + 1e-9f);
        if (iou > THR) m |= 1ull << j;
    }
    g_mask[((size_t)(b * TOPK + i)) * COLB + blockIdx.x] = m;
}

// -------- 4. sequential sweep (one warp/batch) + output write ---------------
// Walk bits in sorted order, skipping suppressed ones via ffsll. Each kept box
// ORs its 94-word suppression row into the shared 'removed' bitmask.
__global__ void sweep_kernel(float* __restrict__ out) {
    int b = blockIdx.x;
    __shared__ unsigned long long removed[COLB];
    __shared__ int kept[NOUT];
    __shared__ int kcount;
    int tid = threadIdx.x;
    if (tid < COLB)
        removed[tid] = (tid == COLB - 1) ? ~((1ull << TAIL_BITS) - 1ull) : 0ull;
    if (tid == 0) kcount = 0;
    __syncthreads();

    if (tid < 32) {
        int cnt = 0;
        for (int w = 0; w < COLB && cnt < NOUT; ++w) {
            unsigned long long avail = ~removed[w];
            while (avail && cnt < NOUT) {
                int bit = __ffsll((long long)avail) - 1;
                avail &= avail - 1;  // clear taken bit (handles zero-area self-IoU=0)
                int i = (w << 6) + bit;
                if (tid == 0) kept[cnt] = i;
                cnt++;
                const unsigned long long* row = &g_mask[((size_t)(b * TOPK + i)) * COLB];
                unsigned long long myw = 0;
                for (int ww = tid; ww < COLB; ww += 32) {
                    unsigned long long rv = row[ww];
                    removed[ww] |= rv;
                    if (ww == w) myw = rv;
                }
                unsigned long long rw = __shfl_sync(0xffffffffu, myw, w & 31);
                avail &= ~rw;
                __syncwarp();
            }
        }
        if (tid == 0) kcount = cnt;
    }
    __syncthreads();

    int kc = kcount;
    for (int k = tid; k < NOUT; k += blockDim.x) {
        float4 v = make_float4(0.f, 0.f, 0.f, 0.f);
        if (k < kc)
            v = reinterpret_cast<const float4*>(g_boxes)[b * TOPK + kept[k]];
        reinterpret_cast<float4*>(out)[b * NOUT + k] = v;
    }
}

// -------- launch --------------------------------------------------------------
extern "C" void kernel_launch(void* const* d_in, const int* in_sizes, int n_in,
                              void* d_out, int out_size) {
    const float* rpn_class = (const float*)d_in[0];
    const float* rpn_bbox  = (const float*)d_in[1];
    const float* anchors   = (const float*)d_in[2];
    float* out = (float*)d_out;

    void *kin, *kout, *vin, *vout, *tmp;
    cudaGetSymbolAddress(&kin,  g_keys_in);
    cudaGetSymbolAddress(&kout, g_keys_out);
    cudaGetSymbolAddress(&vin,  g_vals_in);
    cudaGetSymbolAddress(&vout, g_vals_out);
    cudaGetSymbolAddress(&tmp,  g_temp);

    extract_kernel<<<(TOTAL + 255) / 256, 256>>>(rpn_class);

    size_t temp_bytes = 0;
    cub::DeviceRadixSort::SortPairsDescending(
        nullptr, temp_bytes,
        (const unsigned long long*)kin, (unsigned long long*)kout,
        (const int*)vin, (int*)vout, TOTAL, 0, 35);
    if (temp_bytes <= sizeof(g_temp)) {
        cub::DeviceRadixSort::SortPairsDescending(
            tmp, temp_bytes,
            (const unsigned long long*)kin, (unsigned long long*)kout,
            (const int*)vin, (int*)vout, TOTAL, 0, 35);
    }

    boxes_kernel<<<(BATCH * TOPK + 255) / 256, 256>>>(rpn_bbox, anchors);

    dim3 gmask(COLB, COLB, BATCH);
    iou_kernel<<<gmask, 64>>>();

    sweep_kernel<<<BATCH, 128>>>(out);
}